// round 1
// baseline (speedup 1.0000x reference)
#include <cuda_runtime.h>
#include <math.h>

// ---------------------------------------------------------------------------
// EfficientMultiheadSelfAttention (PVT SRA):  B=4, N=16384 (128x128), C=128,
// HEADS=2 (dh=64), SR=4 -> N'=1024 per batch.
//
// Pipeline:
//   1) conv_kernel : 4x4/stride4 "SAME" conv == non-overlapping patch GEMM
//                    (4096 x 2048 x 128), + bias -> g_xr
//   2) ln_kernel   : LayerNorm over C=128 (in-place on g_xr)
//   3) gemm128     : K = xr@Wk, V = xr@Wv, Q = x@Wq
//   4) attn_kernel : per (b,h): O = softmax(Q K^T / 8) V.
//                    Logits are tiny (|s| < ~0.5) -> exp without max-sub,
//                    accumulate row sums, normalize at end.
//   5) gemm128     : out = att @ Wproj
// ---------------------------------------------------------------------------

#define B_   4
#define N_   16384
#define C_   128
#define NP_  1024         // N' per batch (32*32)
#define DH_  64
#define EPSV 1e-6f
#define SCALE_ 0.125f     // dh^-0.5 = 1/8

// internal scratch (static device globals; no allocation allowed)
__device__ float g_xr[B_ * NP_ * C_];      // conv+LN output      (2 MB)
__device__ float g_k [B_ * NP_ * C_];      // K proj              (2 MB)
__device__ float g_v [B_ * NP_ * C_];      // V proj              (2 MB)
__device__ float g_q [B_ * N_  * C_];      // Q proj              (32 MB)
__device__ float g_att[B_ * N_ * C_];      // attention output    (32 MB)

// ---------------------------------------------------------------------------
// Generic GEMM: C[M x 128] = A[M x 128] @ B[128 x 128].
// Block: 64 rows x 128 cols, 256 threads, thread tile 4x8.
// A stored transposed in smem (k-major) so row reads are float4.
// ---------------------------------------------------------------------------
#define GEMM_SMEM_FLOATS (128 * 68 + 128 * 128)

__global__ void gemm128_kernel(const float* __restrict__ A,
                               const float* __restrict__ Bm,
                               float* __restrict__ Cm) {
    extern __shared__ float sm[];
    float* At = sm;               // [128][68]  (k-major, row minor)
    float* Bs = sm + 128 * 68;    // [128][128]

    const int tid = threadIdx.x;
    const long row0 = (long)blockIdx.x * 64;

    for (int i = tid; i < 128 * 128; i += 256) Bs[i] = Bm[i];
    for (int i = tid; i < 64 * 128; i += 256) {
        int r = i >> 7, k = i & 127;
        At[k * 68 + r] = A[(row0 + r) * 128 + k];
    }
    __syncthreads();

    const int tr = (tid >> 4) << 2;   // 0..60
    const int tc = (tid & 15) << 3;   // 0..120
    float acc[4][8];
#pragma unroll
    for (int r = 0; r < 4; ++r)
#pragma unroll
        for (int c = 0; c < 8; ++c) acc[r][c] = 0.f;

#pragma unroll 4
    for (int kk = 0; kk < 128; ++kk) {
        float4 a  = *(const float4*)(At + kk * 68 + tr);
        float4 b0 = *(const float4*)(Bs + kk * 128 + tc);
        float4 b1 = *(const float4*)(Bs + kk * 128 + tc + 4);
        float av[4] = {a.x, a.y, a.z, a.w};
        float bv[8] = {b0.x, b0.y, b0.z, b0.w, b1.x, b1.y, b1.z, b1.w};
#pragma unroll
        for (int r = 0; r < 4; ++r)
#pragma unroll
            for (int c = 0; c < 8; ++c)
                acc[r][c] = fmaf(av[r], bv[c], acc[r][c]);
    }

#pragma unroll
    for (int r = 0; r < 4; ++r) {
        float4 o0 = make_float4(acc[r][0], acc[r][1], acc[r][2], acc[r][3]);
        float4 o1 = make_float4(acc[r][4], acc[r][5], acc[r][6], acc[r][7]);
        long base = (row0 + tr + r) * 128 + tc;
        *(float4*)(Cm + base)     = o0;
        *(float4*)(Cm + base + 4) = o1;
    }
}

// ---------------------------------------------------------------------------
// Conv 4x4 stride4 (no padding needed) as patch-GEMM + bias.
// Block = one (b, oh) output row: 32 positions x 128 out channels.
// Loop over the 16 patch pixels; each contributes a 128x128 weight slab.
// ---------------------------------------------------------------------------
#define CONV_SMEM_FLOATS (128 * 36 + 128 * 128)

__global__ void conv_kernel(const float* __restrict__ x,
                            const float* __restrict__ w,    // [4][4][128][128]
                            const float* __restrict__ bias,
                            float* __restrict__ out) {
    extern __shared__ float sm[];
    float* At = sm;               // [cin 128][pos 36]
    float* Ws = sm + 128 * 36;    // [cin 128][cout 128]

    const int tid = threadIdx.x;
    const int b  = blockIdx.x >> 5;
    const int oh = blockIdx.x & 31;

    const int tr = (tid >> 4) << 1;   // pos 0..30
    const int tc = (tid & 15) << 3;   // cout 0..120
    float acc[2][8];
#pragma unroll
    for (int r = 0; r < 2; ++r)
#pragma unroll
        for (int c = 0; c < 8; ++c) acc[r][c] = 0.f;

    for (int p = 0; p < 16; ++p) {
        const int ki = p >> 2, kj = p & 3;
        __syncthreads();
        for (int i = tid; i < 32 * 128; i += 256) {
            int pos = i >> 7, cin = i & 127;
            At[cin * 36 + pos] =
                x[((long)b * N_ + (4 * oh + ki) * 128 + 4 * pos + kj) * 128 + cin];
        }
        for (int i = tid; i < 128 * 128; i += 256) Ws[i] = w[p * 16384 + i];
        __syncthreads();

#pragma unroll 4
        for (int kk = 0; kk < 128; ++kk) {
            float2 a  = *(const float2*)(At + kk * 36 + tr);
            float4 b0 = *(const float4*)(Ws + kk * 128 + tc);
            float4 b1 = *(const float4*)(Ws + kk * 128 + tc + 4);
            float av[2] = {a.x, a.y};
            float bv[8] = {b0.x, b0.y, b0.z, b0.w, b1.x, b1.y, b1.z, b1.w};
#pragma unroll
            for (int r = 0; r < 2; ++r)
#pragma unroll
                for (int c = 0; c < 8; ++c)
                    acc[r][c] = fmaf(av[r], bv[c], acc[r][c]);
        }
    }

#pragma unroll
    for (int r = 0; r < 2; ++r) {
        long orow = (long)b * NP_ + oh * 32 + tr + r;
#pragma unroll
        for (int c = 0; c < 8; ++c)
            out[orow * 128 + tc + c] = acc[r][c] + bias[tc + c];
    }
}

// ---------------------------------------------------------------------------
// LayerNorm over C=128, one warp per row, in-place.
// ---------------------------------------------------------------------------
__global__ void ln_kernel(float* __restrict__ xr,
                          const float* __restrict__ gamma,
                          const float* __restrict__ beta) {
    const int row  = blockIdx.x * 4 + (threadIdx.x >> 5);
    const int lane = threadIdx.x & 31;
    float* p = xr + (long)row * 128 + lane * 4;
    float4 v = *(float4*)p;
    float s  = v.x + v.y + v.z + v.w;
    float ss = v.x * v.x + v.y * v.y + v.z * v.z + v.w * v.w;
#pragma unroll
    for (int o = 16; o; o >>= 1) {
        s  += __shfl_xor_sync(0xffffffffu, s,  o);
        ss += __shfl_xor_sync(0xffffffffu, ss, o);
    }
    const float mu   = s * (1.f / 128.f);
    const float var  = ss * (1.f / 128.f) - mu * mu;
    const float rstd = rsqrtf(var + EPSV);
    const float4 g  = *(const float4*)(gamma + lane * 4);
    const float4 be = *(const float4*)(beta  + lane * 4);
    v.x = (v.x - mu) * rstd * g.x + be.x;
    v.y = (v.y - mu) * rstd * g.y + be.y;
    v.z = (v.z - mu) * rstd * g.z + be.z;
    v.w = (v.w - mu) * rstd * g.w + be.w;
    *(float4*)p = v;
}

// ---------------------------------------------------------------------------
// Attention: per (b,h), O = softmax(Q K^T * 1/8) V with tiny logits
// (no max subtraction). Block = 64 queries; keys processed in 8 chunks of 128.
//   GEMM1: S(64x128) = Qt^T Kt  (both k-major in smem, float4 reads)
//   exp + per-row partial sums (smem atomics) ; S stored transposed [key][q]
//   GEMM2: O(64x64) += St^T V
// ---------------------------------------------------------------------------
#define ATTN_SMEM_FLOATS (64 * 68 + 64 * 132 + 128 * 68 + 128 * 68 + 64)

__global__ void attn_kernel(const float* __restrict__ Q,
                            const float* __restrict__ K,
                            const float* __restrict__ V,
                            float* __restrict__ O) {
    extern __shared__ float sm[];
    float* Qt   = sm;                      // [d 64][q 68]
    float* Kt   = Qt + 64 * 68;            // [d 64][key 132]
    float* Vs   = Kt + 64 * 132;           // [key 128][d 68]
    float* St   = Vs + 128 * 68;           // [key 128][q 68]
    float* lsum = St + 128 * 68;           // [64]

    const int tid = threadIdx.x;
    const int bh  = blockIdx.y;
    const int b   = bh >> 1, h = bh & 1;
    const int q0  = blockIdx.x * 64;

    const float* Qb = Q + ((long)b * N_) * 128 + h * DH_;
    const float* Kb = K + ((long)b * NP_) * 128 + h * DH_;
    const float* Vb = V + ((long)b * NP_) * 128 + h * DH_;

    if (tid < 64) lsum[tid] = 0.f;
    for (int i = tid; i < 64 * 64; i += 256) {
        int r = i >> 6, d = i & 63;
        Qt[d * 68 + r] = Qb[(long)(q0 + r) * 128 + d];
    }

    const int rq0 = (tid >> 4) << 2;   // GEMM1 rows (queries) 0..60
    const int ck0 = (tid & 15) << 3;   // GEMM1 cols (keys)    0..120
    const int r2  = (tid >> 4) << 2;   // GEMM2 rows (queries)
    const int c2  = (tid & 15) << 2;   // GEMM2 cols (dh)      0..60

    float oacc[4][4];
#pragma unroll
    for (int r = 0; r < 4; ++r)
#pragma unroll
        for (int c = 0; c < 4; ++c) oacc[r][c] = 0.f;

    for (int kc = 0; kc < 8; ++kc) {
        const int key0 = kc * 128;
        __syncthreads();   // previous GEMM2 done before overwriting Kt/Vs/St
        for (int i = tid; i < 128 * 64; i += 256) {
            int kl = i >> 6, d = i & 63;
            Kt[d * 132 + kl] = Kb[(long)(key0 + kl) * 128 + d];
        }
        for (int i = tid; i < 128 * 64; i += 256) {
            int kl = i >> 6, d = i & 63;
            Vs[kl * 68 + d] = Vb[(long)(key0 + kl) * 128 + d];
        }
        __syncthreads();

        // ---- GEMM1: S = Q K^T ----
        float s[4][8];
#pragma unroll
        for (int r = 0; r < 4; ++r)
#pragma unroll
            for (int c = 0; c < 8; ++c) s[r][c] = 0.f;

#pragma unroll 4
        for (int kk = 0; kk < 64; ++kk) {
            float4 a  = *(const float4*)(Qt + kk * 68 + rq0);
            float4 k0 = *(const float4*)(Kt + kk * 132 + ck0);
            float4 k1 = *(const float4*)(Kt + kk * 132 + ck0 + 4);
            float av[4] = {a.x, a.y, a.z, a.w};
            float bv[8] = {k0.x, k0.y, k0.z, k0.w, k1.x, k1.y, k1.z, k1.w};
#pragma unroll
            for (int r = 0; r < 4; ++r)
#pragma unroll
                for (int c = 0; c < 8; ++c)
                    s[r][c] = fmaf(av[r], bv[c], s[r][c]);
        }

        // ---- exp + row sums + store S^T ----
        float rs[4] = {0.f, 0.f, 0.f, 0.f};
#pragma unroll
        for (int r = 0; r < 4; ++r)
#pragma unroll
            for (int c = 0; c < 8; ++c) {
                float e = __expf(s[r][c] * SCALE_);
                rs[r] += e;
                St[(ck0 + c) * 68 + (rq0 + r)] = e;
            }
#pragma unroll
        for (int r = 0; r < 4; ++r) atomicAdd(&lsum[rq0 + r], rs[r]);
        __syncthreads();

        // ---- GEMM2: O += S V ----
#pragma unroll 4
        for (int kk = 0; kk < 128; ++kk) {
            float4 a = *(const float4*)(St + kk * 68 + r2);
            float4 v = *(const float4*)(Vs + kk * 68 + c2);
            float av[4] = {a.x, a.y, a.z, a.w};
            float vv[4] = {v.x, v.y, v.z, v.w};
#pragma unroll
            for (int r = 0; r < 4; ++r)
#pragma unroll
                for (int c = 0; c < 4; ++c)
                    oacc[r][c] = fmaf(av[r], vv[c], oacc[r][c]);
        }
    }
    __syncthreads();

#pragma unroll
    for (int r = 0; r < 4; ++r) {
        const float inv = 1.f / lsum[r2 + r];
        long base = ((long)b * N_ + q0 + r2 + r) * 128 + h * DH_ + c2;
        float4 o = make_float4(oacc[r][0] * inv, oacc[r][1] * inv,
                               oacc[r][2] * inv, oacc[r][3] * inv);
        *(float4*)(O + base) = o;
    }
}

// ---------------------------------------------------------------------------
extern "C" void kernel_launch(void* const* d_in, const int* in_sizes, int n_in,
                              void* d_out, int out_size) {
    const float* x     = (const float*)d_in[0];
    const float* Wq    = (const float*)d_in[1];
    const float* Wk    = (const float*)d_in[2];
    const float* Wv    = (const float*)d_in[3];
    const float* Wproj = (const float*)d_in[4];
    const float* srk   = (const float*)d_in[5];
    const float* srb   = (const float*)d_in[6];
    const float* gamma = (const float*)d_in[7];
    const float* beta  = (const float*)d_in[8];
    float* out = (float*)d_out;

    float *xr, *k, *v, *q, *att;
    cudaGetSymbolAddress((void**)&xr,  g_xr);
    cudaGetSymbolAddress((void**)&k,   g_k);
    cudaGetSymbolAddress((void**)&v,   g_v);
    cudaGetSymbolAddress((void**)&q,   g_q);
    cudaGetSymbolAddress((void**)&att, g_att);

    const int gemm_smem = GEMM_SMEM_FLOATS * 4;
    const int conv_smem = CONV_SMEM_FLOATS * 4;
    const int attn_smem = ATTN_SMEM_FLOATS * 4;
    cudaFuncSetAttribute(gemm128_kernel, cudaFuncAttributeMaxDynamicSharedMemorySize, gemm_smem);
    cudaFuncSetAttribute(conv_kernel,    cudaFuncAttributeMaxDynamicSharedMemorySize, conv_smem);
    cudaFuncSetAttribute(attn_kernel,    cudaFuncAttributeMaxDynamicSharedMemorySize, attn_smem);

    // 1) conv + bias
    conv_kernel<<<128, 256, conv_smem>>>(x, srk, srb, xr);
    // 2) LayerNorm
    ln_kernel<<<(B_ * NP_) / 4, 128>>>(xr, gamma, beta);
    // 3) projections
    gemm128_kernel<<<(B_ * NP_) / 64, 256, gemm_smem>>>(xr, Wk, k);
    gemm128_kernel<<<(B_ * NP_) / 64, 256, gemm_smem>>>(xr, Wv, v);
    gemm128_kernel<<<(B_ * N_) / 64, 256, gemm_smem>>>(x, Wq, q);
    // 4) attention
    attn_kernel<<<dim3(N_ / 64, B_ * 2), 256, attn_smem>>>(q, k, v, att);
    // 5) output projection
    gemm128_kernel<<<(B_ * N_) / 64, 256, gemm_smem>>>(att, Wproj, out);
}